// round 6
// baseline (speedup 1.0000x reference)
#include <cuda_runtime.h>
#include <math.h>
#include <stdint.h>

#define B_   256
#define T_   256
#define INSZ 512
#define HD   1024
#define NBLK 256
#define NTHR 128

typedef unsigned long long u64;

// Ping-pong hidden state [2][B][4][HD] and inter-stack pred buffers [2][B][INSZ]
__device__ float g_h[2][B_ * 4 * HD];
__device__ float g_pred[2][B_ * INSZ];

// Grid barrier state (sense-reversing; self-resetting count)
__device__ unsigned g_count;
__device__ volatile unsigned g_sense;

__device__ __forceinline__ void grid_barrier(unsigned& ls)
{
    __syncthreads();
    if (threadIdx.x == 0) {
        unsigned s = ls ^ 1u;
        __threadfence();
        if (atomicAdd(&g_count, 1u) == NBLK - 1) {
            g_count = 0;
            __threadfence();
            g_sense = s;            // release
        } else {
            while (g_sense != s) { __nanosleep(32); }
        }
        __threadfence();            // acquire
        ls = s;
    }
    __syncthreads();
}

// ---- packed f32x2 helpers (sm_103a FFMA2 path) ----
__device__ __forceinline__ u64 pack2(float lo, float hi)
{
    u64 r;
    asm("mov.b64 %0, {%1, %2};" : "=l"(r) : "f"(lo), "f"(hi));
    return r;
}
__device__ __forceinline__ void unpack2(u64 v, float& lo, float& hi)
{
    asm("mov.b64 {%0, %1}, %2;" : "=f"(lo), "=f"(hi) : "l"(v));
}
__device__ __forceinline__ void ffma2(u64& d, u64 a, u64 b)
{
    asm("fma.rn.f32x2 %0, %1, %2, %0;" : "+l"(d) : "l"(a), "l"(b));
}

// ---------------------------------------------------------------------------
// 3-gate GEMM accumulate: 32j x 32b tile, 128 threads, microtile 4j x 2b.
// Accumulators: f32x2 pairs over adjacent j: acc[jpair][b].
// Register-prefetch pipeline over 32-wide k chunks.
// ---------------------------------------------------------------------------
__device__ __forceinline__ void accum3(
    const float* __restrict__ A, int astride,
    const float* __restrict__ W, int K, int nk,
    u64 (&au)[2][2], u64 (&ar)[2][2], u64 (&an)[2][2],
    int tx, int ty, int tid,
    float (&As)[32][36], float (&Wus)[32][36],
    float (&Wrs)[32][36], float (&Wns)[32][36])
{
    float4 pa[2];
    float4 pu[2], pr[2], pn[2];

    // prologue: prefetch chunk 0
#pragma unroll
    for (int i = 0; i < 2; i++) {
        int lin = tid + i * 128;
        int bb = lin >> 3, kq = lin & 7;
        pa[i] = __ldcg((const float4*)(A + (size_t)bb * astride + kq * 4));
    }
#pragma unroll
    for (int i = 0; i < 2; i++) {
        int lin = tid + i * 128;
        int jj = lin >> 3, kq = lin & 7;
        size_t ro = (size_t)jj * K + kq * 4;
        pu[i] = *(const float4*)(W + ro);
        pr[i] = *(const float4*)(W + (size_t)HD * K + ro);
        pn[i] = *(const float4*)(W + (size_t)(2 * HD) * K + ro);
    }

    for (int k0 = 0; k0 < nk; k0 += 32) {
        __syncthreads();
#pragma unroll
        for (int i = 0; i < 2; i++) {
            int lin = tid + i * 128;
            int bb = lin >> 3, kq = lin & 7;
            As[kq * 4 + 0][bb] = pa[i].x; As[kq * 4 + 1][bb] = pa[i].y;
            As[kq * 4 + 2][bb] = pa[i].z; As[kq * 4 + 3][bb] = pa[i].w;
        }
#pragma unroll
        for (int i = 0; i < 2; i++) {
            int lin = tid + i * 128;
            int jj = lin >> 3, kq = lin & 7;
            Wus[kq * 4 + 0][jj] = pu[i].x; Wus[kq * 4 + 1][jj] = pu[i].y;
            Wus[kq * 4 + 2][jj] = pu[i].z; Wus[kq * 4 + 3][jj] = pu[i].w;
            Wrs[kq * 4 + 0][jj] = pr[i].x; Wrs[kq * 4 + 1][jj] = pr[i].y;
            Wrs[kq * 4 + 2][jj] = pr[i].z; Wrs[kq * 4 + 3][jj] = pr[i].w;
            Wns[kq * 4 + 0][jj] = pn[i].x; Wns[kq * 4 + 1][jj] = pn[i].y;
            Wns[kq * 4 + 2][jj] = pn[i].z; Wns[kq * 4 + 3][jj] = pn[i].w;
        }
        __syncthreads();
        // prefetch next chunk while computing this one
        int kn = k0 + 32;
        if (kn < nk) {
#pragma unroll
            for (int i = 0; i < 2; i++) {
                int lin = tid + i * 128;
                int bb = lin >> 3, kq = lin & 7;
                pa[i] = __ldcg((const float4*)(A + (size_t)bb * astride + (kn + kq * 4)));
            }
#pragma unroll
            for (int i = 0; i < 2; i++) {
                int lin = tid + i * 128;
                int jj = lin >> 3, kq = lin & 7;
                size_t ro = (size_t)jj * K + (kn + kq * 4);
                pu[i] = *(const float4*)(W + ro);
                pr[i] = *(const float4*)(W + (size_t)HD * K + ro);
                pn[i] = *(const float4*)(W + (size_t)(2 * HD) * K + ro);
            }
        }
#pragma unroll
        for (int kk = 0; kk < 32; kk++) {
            float2 a2 = *(const float2*)&As[kk][ty * 2];
            u64 Ab[2];
            Ab[0] = pack2(a2.x, a2.x);
            Ab[1] = pack2(a2.y, a2.y);
            ulonglong2 wu = *(const ulonglong2*)&Wus[kk][tx * 4];
            ulonglong2 wr = *(const ulonglong2*)&Wrs[kk][tx * 4];
            ulonglong2 wn = *(const ulonglong2*)&Wns[kk][tx * 4];
#pragma unroll
            for (int i = 0; i < 2; i++) {
                ffma2(au[0][i], Ab[i], wu.x); ffma2(au[1][i], Ab[i], wu.y);
                ffma2(ar[0][i], Ab[i], wr.x); ffma2(ar[1][i], Ab[i], wr.y);
                ffma2(an[0][i], Ab[i], wn.x); ffma2(an[1][i], Ab[i], wn.y);
            }
        }
    }
}

// Pred accumulate: 16o x 32b tile, 128 threads, microtile 2o x 2b.
// Accumulators packed over adjacent b (u64 straight from As).
__device__ __forceinline__ void accum1(
    const float* __restrict__ A, int astride,
    const float* __restrict__ W, int wstride, int nk,
    u64 (&acc)[2],               // [o], packed over b-pair
    int tx, int ty, int tid,
    float (&As)[32][36], float (&Ws)[32][36])
{
    float4 pa[2];
    float4 pw;

#pragma unroll
    for (int i = 0; i < 2; i++) {
        int lin = tid + i * 128;
        int bb = lin >> 3, kq = lin & 7;
        pa[i] = __ldcg((const float4*)(A + (size_t)bb * astride + kq * 4));
    }
    {
        int jj = tid >> 3, kq = tid & 7;   // 16 rows x 8 float4 = 128
        pw = *(const float4*)(W + (size_t)jj * wstride + kq * 4);
    }

    for (int k0 = 0; k0 < nk; k0 += 32) {
        __syncthreads();
#pragma unroll
        for (int i = 0; i < 2; i++) {
            int lin = tid + i * 128;
            int bb = lin >> 3, kq = lin & 7;
            As[kq * 4 + 0][bb] = pa[i].x; As[kq * 4 + 1][bb] = pa[i].y;
            As[kq * 4 + 2][bb] = pa[i].z; As[kq * 4 + 3][bb] = pa[i].w;
        }
        {
            int jj = tid >> 3, kq = tid & 7;
            Ws[kq * 4 + 0][jj] = pw.x; Ws[kq * 4 + 1][jj] = pw.y;
            Ws[kq * 4 + 2][jj] = pw.z; Ws[kq * 4 + 3][jj] = pw.w;
        }
        __syncthreads();
        int kn = k0 + 32;
        if (kn < nk) {
#pragma unroll
            for (int i = 0; i < 2; i++) {
                int lin = tid + i * 128;
                int bb = lin >> 3, kq = lin & 7;
                pa[i] = __ldcg((const float4*)(A + (size_t)bb * astride + (kn + kq * 4)));
            }
            int jj = tid >> 3, kq = tid & 7;
            pw = *(const float4*)(W + (size_t)jj * wstride + (kn + kq * 4));
        }
#pragma unroll
        for (int kk = 0; kk < 32; kk++) {
            u64 a = *(const u64*)&As[kk][ty * 2];     // b-pair
            float2 wf = *(const float2*)&Ws[kk][tx * 2];
            u64 W0 = pack2(wf.x, wf.x);
            u64 W1 = pack2(wf.y, wf.y);
            ffma2(acc[0], W0, a);
            ffma2(acc[1], W1, a);
        }
    }
}

// ---------------------------------------------------------------------------
// One persistent kernel: entire SGRU sequence + log_softmax + h copy-out.
// grid = 256 blocks (2 per SM), 128 threads.
// ---------------------------------------------------------------------------
__global__ void __launch_bounds__(NTHR, 2) sgru_kernel(
    const float* __restrict__ xb, const float* __restrict__ h0,
    const float* __restrict__ Wx, const float* __restrict__ bx,
    const float* __restrict__ Wh, const float* __restrict__ bh,
    const float* __restrict__ Wo, const float* __restrict__ bo,
    float* __restrict__ out)
{
    __shared__ __align__(16) float As[32][36];
    __shared__ __align__(16) float Wus[32][36];
    __shared__ __align__(16) float Wrs[32][36];
    __shared__ __align__(16) float Wns[32][36];

    int tid = threadIdx.x;
    int bid = blockIdx.x;
    unsigned ls = g_sense;   // read before any block can flip it

    // ---- init: h0 -> g_h[0] ----
    {
        int g = bid * NTHR + tid;
        const float4* s4 = (const float4*)h0;
        float4* d4 = (float4*)g_h[0];
#pragma unroll 1
        for (int i = g; i < B_ * 4 * HD / 4; i += NBLK * NTHR) d4[i] = s4[i];
    }
    grid_barrier(ls);

#pragma unroll 1
    for (int t = 0; t < T_; t++) {
        int rd = t & 1, wr = rd ^ 1;
#pragma unroll 1
        for (int s = 0; s < 4; s++) {
            int wi = (s == 3) ? 2 : s;   // faithful to the source bug

            const float* x;
            int xstride;
            if (s == 0) { x = xb + (size_t)t * INSZ; xstride = T_ * INSZ; }
            else        { x = g_pred[(s - 1) & 1];   xstride = INSZ; }

            // ===== gate phase: 32 j-tiles (32) x 8 b-tiles (32) =====
            {
                int tx = tid & 7, ty = tid >> 3;     // tx: 8 x 4j = 32j, ty: 16 x 2b = 32b
                int j0 = (bid & 31) * 32;
                int b0 = (bid >> 5) * 32;
                const float* Wxp = Wx + (size_t)wi * 3 * HD * INSZ + (size_t)j0 * INSZ;
                const float* Whp = Wh + (size_t)wi * 3 * HD * HD + (size_t)j0 * HD;
                const float* bx3 = bx + wi * 3 * HD;
                const float* bh3 = bh + wi * 3 * HD;
                const float* hrd = g_h[rd] + s * HD;
                float* hwr = g_h[wr] + s * HD;

                u64 au[2][2], ar[2][2], axn[2][2], ahn[2][2];
#pragma unroll
                for (int p = 0; p < 2; p++) {
                    int jg = j0 + tx * 4 + p * 2;
                    u64 bu = pack2(bx3[jg] + bh3[jg], bx3[jg + 1] + bh3[jg + 1]);
                    u64 br = pack2(bx3[HD + jg] + bh3[HD + jg],
                                   bx3[HD + jg + 1] + bh3[HD + jg + 1]);
                    u64 bxn = pack2(bx3[2 * HD + jg], bx3[2 * HD + jg + 1]);
                    u64 bhn = pack2(bh3[2 * HD + jg], bh3[2 * HD + jg + 1]);
#pragma unroll
                    for (int i = 0; i < 2; i++) {
                        au[p][i] = bu; ar[p][i] = br;
                        axn[p][i] = bxn; ahn[p][i] = bhn;
                    }
                }
                accum3(x + (size_t)b0 * xstride, xstride, Wxp, INSZ, INSZ,
                       au, ar, axn, tx, ty, tid, As, Wus, Wrs, Wns);
                accum3(hrd + (size_t)b0 * (4 * HD), 4 * HD, Whp, HD, HD,
                       au, ar, ahn, tx, ty, tid, As, Wus, Wrs, Wns);

#pragma unroll
                for (int i = 0; i < 2; i++) {
                    int b = b0 + ty * 2 + i;
                    int jg = j0 + tx * 4;
                    float4 hold = __ldcg((const float4*)(hrd + (size_t)b * (4 * HD) + jg));
                    float ho[4] = {hold.x, hold.y, hold.z, hold.w};
                    float uv[4], rv[4], xnv[4], hnv[4];
#pragma unroll
                    for (int p = 0; p < 2; p++) {
                        unpack2(au[p][i], uv[p * 2], uv[p * 2 + 1]);
                        unpack2(ar[p][i], rv[p * 2], rv[p * 2 + 1]);
                        unpack2(axn[p][i], xnv[p * 2], xnv[p * 2 + 1]);
                        unpack2(ahn[p][i], hnv[p * 2], hnv[p * 2 + 1]);
                    }
                    float4 hv;
                    float* hvp = &hv.x;
#pragma unroll
                    for (int jj = 0; jj < 4; jj++) {
                        float u = 1.0f / (1.0f + expf(-uv[jj]));
                        float r = 1.0f / (1.0f + expf(-rv[jj]));
                        float n = tanhf(xnv[jj] + r * hnv[jj]);
                        hvp[jj] = u * ho[jj] + (1.0f - u) * n;
                    }
                    *(float4*)(hwr + (size_t)b * (4 * HD) + jg) = hv;
                }
            }
            grid_barrier(ls);

            // ===== pred phase: 32 o-tiles (16) x 8 b-tiles (32) =====
            {
                int tx = tid & 7, ty = tid >> 3;     // tx: 8 x 2o = 16o, ty: 16 x 2b = 32b
                int o0 = (bid & 31) * 16;
                int b0 = (bid >> 5) * 32;
                const float* Wop = Wo + (size_t)wi * INSZ * (HD + INSZ) + (size_t)o0 * (HD + INSZ);
                const float* bop = bo + wi * INSZ;
                const float* hn = g_h[wr] + s * HD;

                u64 acc[2];   // [o], packed over b-pair
                acc[0] = pack2(bop[o0 + tx * 2], bop[o0 + tx * 2]);
                acc[1] = pack2(bop[o0 + tx * 2 + 1], bop[o0 + tx * 2 + 1]);

                accum1(x + (size_t)b0 * xstride, xstride,
                       Wop, HD + INSZ, INSZ, acc, tx, ty, tid, As, Wus);
                accum1(hn + (size_t)b0 * (4 * HD), 4 * HD,
                       Wop + INSZ, HD + INSZ, HD, acc, tx, ty, tid, As, Wus);

                float* outp; int ostr;
                if (s == 3) { outp = out + (size_t)t * INSZ; ostr = T_ * INSZ; }
                else        { outp = g_pred[s & 1];          ostr = INSZ; }

                float o0b[2], o1b[2];
                unpack2(acc[0], o0b[0], o0b[1]);
                unpack2(acc[1], o1b[0], o1b[1]);
#pragma unroll
                for (int i = 0; i < 2; i++) {
                    int b = b0 + ty * 2 + i;
                    float2 v = make_float2(o0b[i], o1b[i]);
                    *(float2*)(outp + (size_t)b * ostr + (o0 + tx * 2)) = v;
                }
            }
            grid_barrier(ls);
        }
    }

    // ---- copy final h (in g_h[0]) to out tail ----
    {
        int g = bid * NTHR + tid;
        const float4* s4 = (const float4*)g_h[0];
        float4* d4 = (float4*)(out + (size_t)B_ * T_ * INSZ);
#pragma unroll 1
        for (int i = g; i < B_ * 4 * HD / 4; i += NBLK * NTHR) d4[i] = __ldcg(s4 + i);
    }

    // ---- log_softmax over each 512-wide pred row ----
    {
        int w = tid >> 5, ln = tid & 31;      // 4 warps per block
        int gw = bid * 4 + w;
#pragma unroll 1
        for (int r = gw; r < B_ * T_; r += NBLK * 4) {
            float* p = out + (size_t)r * INSZ;
            float v[16];
            float m = -1e30f;
#pragma unroll
            for (int i = 0; i < 16; i++) {
                v[i] = __ldcg(p + ln + i * 32);
                m = fmaxf(m, v[i]);
            }
#pragma unroll
            for (int off = 16; off > 0; off >>= 1)
                m = fmaxf(m, __shfl_xor_sync(0xffffffffu, m, off));
            float sm = 0.0f;
#pragma unroll
            for (int i = 0; i < 16; i++) sm += expf(v[i] - m);
#pragma unroll
            for (int off = 16; off > 0; off >>= 1)
                sm += __shfl_xor_sync(0xffffffffu, sm, off);
            float lsv = m + logf(sm);
#pragma unroll
            for (int i = 0; i < 16; i++) p[ln + i * 32] = v[i] - lsv;
        }
    }
}

// ---------------------------------------------------------------------------
extern "C" void kernel_launch(void* const* d_in, const int* in_sizes, int n_in,
                              void* d_out, int out_size)
{
    const float* xb = (const float*)d_in[0];
    const float* h0 = (const float*)d_in[1];
    const float* Wx = (const float*)d_in[2];
    const float* bx = (const float*)d_in[3];
    const float* Wh = (const float*)d_in[4];
    const float* bh = (const float*)d_in[5];
    const float* Wo = (const float*)d_in[6];
    const float* bo = (const float*)d_in[7];
    float* out = (float*)d_out;

    sgru_kernel<<<NBLK, NTHR>>>(xb, h0, Wx, bx, Wh, bh, Wo, bo, out);
}

// round 9
// speedup vs baseline: 1.5407x; 1.5407x over previous
#include <cuda_runtime.h>
#include <math.h>
#include <stdint.h>

#define B_   256
#define T_   256
#define INSZ 512
#define HD   1024
#define NBLK 128
#define NTHR 256

typedef unsigned long long u64;

// Ping-pong hidden state [2][B][4][HD] and inter-stack pred buffers [2][B][INSZ]
__device__ float g_h[2][B_ * 4 * HD];
__device__ float g_pred[2][B_ * INSZ];

// Grid barrier state (sense-reversing; self-resetting count)
__device__ unsigned g_count;
__device__ volatile unsigned g_sense;

__device__ __forceinline__ void grid_barrier(unsigned& ls)
{
    __syncthreads();
    if (threadIdx.x == 0) {
        unsigned s = ls ^ 1u;
        __threadfence();
        if (atomicAdd(&g_count, 1u) == NBLK - 1) {
            g_count = 0;
            __threadfence();
            g_sense = s;            // release
        } else {
            while (g_sense != s) { __nanosleep(32); }
        }
        __threadfence();            // acquire
        ls = s;
    }
    __syncthreads();
}

// ---- packed f32x2 helpers (sm_103 FFMA2 path) ----
__device__ __forceinline__ u64 pack2(float lo, float hi)
{
    u64 r;
    asm("mov.b64 %0, {%1, %2};" : "=l"(r) : "f"(lo), "f"(hi));
    return r;
}
__device__ __forceinline__ void unpack2(u64 v, float& lo, float& hi)
{
    asm("mov.b64 {%0, %1}, %2;" : "=f"(lo), "=f"(hi) : "l"(v));
}
__device__ __forceinline__ void ffma2(u64& d, u64 a, u64 b)
{
    asm("fma.rn.f32x2 %0, %1, %2, %0;" : "+l"(d) : "l"(a), "l"(b));
}
__device__ __forceinline__ u64 addf2(u64 a, u64 b)
{
    u64 r;
    asm("add.rn.f32x2 %0, %1, %2;" : "=l"(r) : "l"(a), "l"(b));
    return r;
}

// ---------------------------------------------------------------------------
// 3-gate GEMM accumulate: 32j x 64b tile, 256 threads.
// Output microtile 4j x 4b held by 128 "output" threads (tid&127); the k-loop
// of each 32-chunk is SPLIT between the two 128-thread halves (kh = 0 or 16).
// All 256 threads cooperate on loads. Register-prefetch over 32-wide k chunks.
// ---------------------------------------------------------------------------
__device__ __forceinline__ void accum3(
    const float* __restrict__ A, int astride,
    const float* __restrict__ W, int K, int nk,
    u64 (&au)[2][4], u64 (&ar)[2][4], u64 (&an)[2][4],
    int tx, int ty, int kh, int tid,
    float (&As)[32][68], float (&Wus)[32][36],
    float (&Wrs)[32][36], float (&Wns)[32][36])
{
    float4 pa[2];
    float4 pu, pr, pn;

    // prologue: prefetch chunk 0
#pragma unroll
    for (int i = 0; i < 2; i++) {
        int lin = tid + i * 256;
        int bb = lin >> 3, kq = lin & 7;
        pa[i] = __ldcg((const float4*)(A + (size_t)bb * astride + kq * 4));
    }
    {
        int jj = tid >> 3, kq = tid & 7;
        size_t ro = (size_t)jj * K + kq * 4;
        pu = *(const float4*)(W + ro);
        pr = *(const float4*)(W + (size_t)HD * K + ro);
        pn = *(const float4*)(W + (size_t)(2 * HD) * K + ro);
    }

    for (int k0 = 0; k0 < nk; k0 += 32) {
        __syncthreads();
#pragma unroll
        for (int i = 0; i < 2; i++) {
            int lin = tid + i * 256;
            int bb = lin >> 3, kq = lin & 7;
            As[kq * 4 + 0][bb] = pa[i].x; As[kq * 4 + 1][bb] = pa[i].y;
            As[kq * 4 + 2][bb] = pa[i].z; As[kq * 4 + 3][bb] = pa[i].w;
        }
        {
            int jj = tid >> 3, kq = tid & 7;
            Wus[kq * 4 + 0][jj] = pu.x; Wus[kq * 4 + 1][jj] = pu.y;
            Wus[kq * 4 + 2][jj] = pu.z; Wus[kq * 4 + 3][jj] = pu.w;
            Wrs[kq * 4 + 0][jj] = pr.x; Wrs[kq * 4 + 1][jj] = pr.y;
            Wrs[kq * 4 + 2][jj] = pr.z; Wrs[kq * 4 + 3][jj] = pr.w;
            Wns[kq * 4 + 0][jj] = pn.x; Wns[kq * 4 + 1][jj] = pn.y;
            Wns[kq * 4 + 2][jj] = pn.z; Wns[kq * 4 + 3][jj] = pn.w;
        }
        __syncthreads();
        // prefetch next chunk while computing this one
        int kn = k0 + 32;
        if (kn < nk) {
#pragma unroll
            for (int i = 0; i < 2; i++) {
                int lin = tid + i * 256;
                int bb = lin >> 3, kq = lin & 7;
                pa[i] = __ldcg((const float4*)(A + (size_t)bb * astride + (kn + kq * 4)));
            }
            int jj = tid >> 3, kq = tid & 7;
            size_t ro = (size_t)jj * K + (kn + kq * 4);
            pu = *(const float4*)(W + ro);
            pr = *(const float4*)(W + (size_t)HD * K + ro);
            pn = *(const float4*)(W + (size_t)(2 * HD) * K + ro);
        }
#pragma unroll
        for (int kk = 0; kk < 16; kk++) {
            int ka = kh + kk;
            float4 a4 = *(const float4*)&As[ka][ty * 4];
            u64 Ab[4];
            Ab[0] = pack2(a4.x, a4.x); Ab[1] = pack2(a4.y, a4.y);
            Ab[2] = pack2(a4.z, a4.z); Ab[3] = pack2(a4.w, a4.w);
            ulonglong2 wu = *(const ulonglong2*)&Wus[ka][tx * 4];
            ulonglong2 wr = *(const ulonglong2*)&Wrs[ka][tx * 4];
            ulonglong2 wn = *(const ulonglong2*)&Wns[ka][tx * 4];
#pragma unroll
            for (int i = 0; i < 4; i++) {
                ffma2(au[0][i], Ab[i], wu.x); ffma2(au[1][i], Ab[i], wu.y);
                ffma2(ar[0][i], Ab[i], wr.x); ffma2(ar[1][i], Ab[i], wr.y);
                ffma2(an[0][i], Ab[i], wn.x); ffma2(an[1][i], Ab[i], wn.y);
            }
        }
    }
}

// Pred accumulate: 16o x 64b tile, 256 threads, k-split halves.
// Output microtile 2o x 4b (acc packed over b-pairs) on 128 output threads.
__device__ __forceinline__ void accum1(
    const float* __restrict__ A, int astride,
    const float* __restrict__ W, int wstride, int nk,
    u64 (&acc)[2][2],            // [o][bpair]
    int tx, int ty, int kh, int tid,
    float (&As)[32][68], float (&Ws)[32][36])
{
    float4 pa[2];
    float4 pw;

#pragma unroll
    for (int i = 0; i < 2; i++) {
        int lin = tid + i * 256;
        int bb = lin >> 3, kq = lin & 7;
        pa[i] = __ldcg((const float4*)(A + (size_t)bb * astride + kq * 4));
    }
    if (tid < 128) {
        int jj = tid >> 3, kq = tid & 7;   // 16 rows x 8 float4
        pw = *(const float4*)(W + (size_t)jj * wstride + kq * 4);
    }

    for (int k0 = 0; k0 < nk; k0 += 32) {
        __syncthreads();
#pragma unroll
        for (int i = 0; i < 2; i++) {
            int lin = tid + i * 256;
            int bb = lin >> 3, kq = lin & 7;
            As[kq * 4 + 0][bb] = pa[i].x; As[kq * 4 + 1][bb] = pa[i].y;
            As[kq * 4 + 2][bb] = pa[i].z; As[kq * 4 + 3][bb] = pa[i].w;
        }
        if (tid < 128) {
            int jj = tid >> 3, kq = tid & 7;
            Ws[kq * 4 + 0][jj] = pw.x; Ws[kq * 4 + 1][jj] = pw.y;
            Ws[kq * 4 + 2][jj] = pw.z; Ws[kq * 4 + 3][jj] = pw.w;
        }
        __syncthreads();
        int kn = k0 + 32;
        if (kn < nk) {
#pragma unroll
            for (int i = 0; i < 2; i++) {
                int lin = tid + i * 256;
                int bb = lin >> 3, kq = lin & 7;
                pa[i] = __ldcg((const float4*)(A + (size_t)bb * astride + (kn + kq * 4)));
            }
            if (tid < 128) {
                int jj = tid >> 3, kq = tid & 7;
                pw = *(const float4*)(W + (size_t)jj * wstride + (kn + kq * 4));
            }
        }
#pragma unroll
        for (int kk = 0; kk < 16; kk++) {
            int ka = kh + kk;
            ulonglong2 a2 = *(const ulonglong2*)&As[ka][ty * 4];   // (b0,b1),(b2,b3)
            float2 wf = *(const float2*)&Ws[ka][tx * 2];
            u64 W0 = pack2(wf.x, wf.x);
            u64 W1 = pack2(wf.y, wf.y);
            ffma2(acc[0][0], W0, a2.x); ffma2(acc[0][1], W0, a2.y);
            ffma2(acc[1][0], W1, a2.x); ffma2(acc[1][1], W1, a2.y);
        }
    }
}

// ---------------------------------------------------------------------------
// One persistent kernel: entire SGRU sequence + log_softmax + h copy-out.
// grid = 128 blocks, 256 threads (2 warps/SMSP via k-split).
// ---------------------------------------------------------------------------
__global__ void __launch_bounds__(NTHR) sgru_kernel(
    const float* __restrict__ xb, const float* __restrict__ h0,
    const float* __restrict__ Wx, const float* __restrict__ bx,
    const float* __restrict__ Wh, const float* __restrict__ bh,
    const float* __restrict__ Wo, const float* __restrict__ bo,
    float* __restrict__ out)
{
    __shared__ __align__(16) float As[32][68];
    __shared__ __align__(16) float Wus[32][36];
    __shared__ __align__(16) float Wrs[32][36];
    __shared__ __align__(16) float Wns[32][36];
    __shared__ __align__(16) u64 red[128][17];

    int tid = threadIdx.x;
    int bid = blockIdx.x;
    int tid2 = tid & 127, half = tid >> 7, kh = half * 16;
    unsigned ls = g_sense;   // read before any block can flip it

    // ---- init: h0 -> g_h[0] ----
    {
        int g = bid * NTHR + tid;
        const float4* s4 = (const float4*)h0;
        float4* d4 = (float4*)g_h[0];
#pragma unroll 1
        for (int i = g; i < B_ * 4 * HD / 4; i += NBLK * NTHR) d4[i] = s4[i];
    }
    grid_barrier(ls);

#pragma unroll 1
    for (int t = 0; t < T_; t++) {
        int rd = t & 1, wr = rd ^ 1;
#pragma unroll 1
        for (int s = 0; s < 4; s++) {
            int wi = (s == 3) ? 2 : s;   // faithful to the source bug

            const float* x;
            int xstride;
            if (s == 0) { x = xb + (size_t)t * INSZ; xstride = T_ * INSZ; }
            else        { x = g_pred[(s - 1) & 1];   xstride = INSZ; }

            // ===== gate phase: 32 j-tiles (32) x 4 b-tiles (64) =====
            {
                int tx = tid2 & 7, ty = tid2 >> 3;   // 8 x 4j = 32j, 16 x 4b = 64b
                int j0 = (bid & 31) * 32;
                int b0 = (bid >> 5) * 64;
                const float* Wxp = Wx + (size_t)wi * 3 * HD * INSZ + (size_t)j0 * INSZ;
                const float* Whp = Wh + (size_t)wi * 3 * HD * HD + (size_t)j0 * HD;
                const float* bx3 = bx + wi * 3 * HD;
                const float* bh3 = bh + wi * 3 * HD;
                const float* hrd = g_h[rd] + s * HD;
                float* hwr = g_h[wr] + s * HD;

                u64 au[2][4], ar[2][4], axn[2][4], ahn[2][4];
                if (half == 0) {
#pragma unroll
                    for (int p = 0; p < 2; p++) {
                        int jg = j0 + tx * 4 + p * 2;
                        u64 bu = pack2(bx3[jg] + bh3[jg], bx3[jg + 1] + bh3[jg + 1]);
                        u64 br = pack2(bx3[HD + jg] + bh3[HD + jg],
                                       bx3[HD + jg + 1] + bh3[HD + jg + 1]);
                        u64 bxn = pack2(bx3[2 * HD + jg], bx3[2 * HD + jg + 1]);
                        u64 bhn = pack2(bh3[2 * HD + jg], bh3[2 * HD + jg + 1]);
#pragma unroll
                        for (int i = 0; i < 4; i++) {
                            au[p][i] = bu; ar[p][i] = br;
                            axn[p][i] = bxn; ahn[p][i] = bhn;
                        }
                    }
                } else {
#pragma unroll
                    for (int p = 0; p < 2; p++)
#pragma unroll
                        for (int i = 0; i < 4; i++) {
                            au[p][i] = 0; ar[p][i] = 0;
                            axn[p][i] = 0; ahn[p][i] = 0;
                        }
                }
                accum3(x + (size_t)b0 * xstride, xstride, Wxp, INSZ, INSZ,
                       au, ar, axn, tx, ty, kh, tid, As, Wus, Wrs, Wns);
                accum3(hrd + (size_t)b0 * (4 * HD), 4 * HD, Whp, HD, HD,
                       au, ar, ahn, tx, ty, kh, tid, As, Wus, Wrs, Wns);

                // cross-half reduction, round 1: u and r
                __syncthreads();
                if (half) {
#pragma unroll
                    for (int p = 0; p < 2; p++)
#pragma unroll
                        for (int i = 0; i < 4; i++) {
                            red[tid2][p * 4 + i] = au[p][i];
                            red[tid2][8 + p * 4 + i] = ar[p][i];
                        }
                }
                __syncthreads();
                if (!half) {
#pragma unroll
                    for (int p = 0; p < 2; p++)
#pragma unroll
                        for (int i = 0; i < 4; i++) {
                            au[p][i] = addf2(au[p][i], red[tid2][p * 4 + i]);
                            ar[p][i] = addf2(ar[p][i], red[tid2][8 + p * 4 + i]);
                        }
                }
                // round 2: xn and hn
                __syncthreads();
                if (half) {
#pragma unroll
                    for (int p = 0; p < 2; p++)
#pragma unroll
                        for (int i = 0; i < 4; i++) {
                            red[tid2][p * 4 + i] = axn[p][i];
                            red[tid2][8 + p * 4 + i] = ahn[p][i];
                        }
                }
                __syncthreads();
                if (!half) {
#pragma unroll
                    for (int p = 0; p < 2; p++)
#pragma unroll
                        for (int i = 0; i < 4; i++) {
                            axn[p][i] = addf2(axn[p][i], red[tid2][p * 4 + i]);
                            ahn[p][i] = addf2(ahn[p][i], red[tid2][8 + p * 4 + i]);
                        }

#pragma unroll
                    for (int i = 0; i < 4; i++) {
                        int b = b0 + ty * 4 + i;
                        int jg = j0 + tx * 4;
                        float4 hold = __ldcg((const float4*)(hrd + (size_t)b * (4 * HD) + jg));
                        float ho[4] = {hold.x, hold.y, hold.z, hold.w};
                        float uv[4], rv[4], xnv[4], hnv[4];
#pragma unroll
                        for (int p = 0; p < 2; p++) {
                            unpack2(au[p][i], uv[p * 2], uv[p * 2 + 1]);
                            unpack2(ar[p][i], rv[p * 2], rv[p * 2 + 1]);
                            unpack2(axn[p][i], xnv[p * 2], xnv[p * 2 + 1]);
                            unpack2(ahn[p][i], hnv[p * 2], hnv[p * 2 + 1]);
                        }
                        float4 hv;
                        float* hvp = &hv.x;
#pragma unroll
                        for (int jj = 0; jj < 4; jj++) {
                            float u = 1.0f / (1.0f + expf(-uv[jj]));
                            float r = 1.0f / (1.0f + expf(-rv[jj]));
                            float n = tanhf(xnv[jj] + r * hnv[jj]);
                            hvp[jj] = u * ho[jj] + (1.0f - u) * n;
                        }
                        *(float4*)(hwr + (size_t)b * (4 * HD) + jg) = hv;
                    }
                }
            }
            grid_barrier(ls);

            // ===== pred phase: 32 o-tiles (16) x 4 b-tiles (64) =====
            {
                int tx = tid2 & 7, ty = tid2 >> 3;   // 8 x 2o = 16o, 16 x 4b = 64b
                int o0 = (bid & 31) * 16;
                int b0 = (bid >> 5) * 64;
                const float* Wop = Wo + (size_t)wi * INSZ * (HD + INSZ) + (size_t)o0 * (HD + INSZ);
                const float* bop = bo + wi * INSZ;
                const float* hn = g_h[wr] + s * HD;

                u64 acc[2][2];   // [o][bpair]
                if (half == 0) {
                    acc[0][0] = acc[0][1] = pack2(bop[o0 + tx * 2], bop[o0 + tx * 2]);
                    acc[1][0] = acc[1][1] = pack2(bop[o0 + tx * 2 + 1], bop[o0 + tx * 2 + 1]);
                } else {
                    acc[0][0] = acc[0][1] = 0;
                    acc[1][0] = acc[1][1] = 0;
                }

                accum1(x + (size_t)b0 * xstride, xstride,
                       Wop, HD + INSZ, INSZ, acc, tx, ty, kh, tid, As, Wus);
                accum1(hn + (size_t)b0 * (4 * HD), 4 * HD,
                       Wop + INSZ, HD + INSZ, HD, acc, tx, ty, kh, tid, As, Wus);

                // cross-half reduction
                __syncthreads();
                if (half) {
                    red[tid2][0] = acc[0][0]; red[tid2][1] = acc[0][1];
                    red[tid2][2] = acc[1][0]; red[tid2][3] = acc[1][1];
                }
                __syncthreads();
                if (!half) {
                    acc[0][0] = addf2(acc[0][0], red[tid2][0]);
                    acc[0][1] = addf2(acc[0][1], red[tid2][1]);
                    acc[1][0] = addf2(acc[1][0], red[tid2][2]);
                    acc[1][1] = addf2(acc[1][1], red[tid2][3]);

                    float* outp; int ostr;
                    if (s == 3) { outp = out + (size_t)t * INSZ; ostr = T_ * INSZ; }
                    else        { outp = g_pred[s & 1];          ostr = INSZ; }

                    float o0b[4], o1b[4];
                    unpack2(acc[0][0], o0b[0], o0b[1]); unpack2(acc[0][1], o0b[2], o0b[3]);
                    unpack2(acc[1][0], o1b[0], o1b[1]); unpack2(acc[1][1], o1b[2], o1b[3]);
#pragma unroll
                    for (int i = 0; i < 4; i++) {
                        int b = b0 + ty * 4 + i;
                        float2 v = make_float2(o0b[i], o1b[i]);
                        *(float2*)(outp + (size_t)b * ostr + (o0 + tx * 2)) = v;
                    }
                }
            }
            grid_barrier(ls);
        }
    }

    // ---- copy final h (in g_h[0]) to out tail ----
    {
        int g = bid * NTHR + tid;
        const float4* s4 = (const float4*)g_h[0];
        float4* d4 = (float4*)(out + (size_t)B_ * T_ * INSZ);
#pragma unroll 1
        for (int i = g; i < B_ * 4 * HD / 4; i += NBLK * NTHR) d4[i] = __ldcg(s4 + i);
    }

    // ---- log_softmax over each 512-wide pred row ----
    {
        int w = tid >> 5, ln = tid & 31;      // 8 warps per block
        int gw = bid * 8 + w;
#pragma unroll 1
        for (int r = gw; r < B_ * T_; r += NBLK * 8) {
            float* p = out + (size_t)r * INSZ;
            float v[16];
            float m = -1e30f;
#pragma unroll
            for (int i = 0; i < 16; i++) {
                v[i] = __ldcg(p + ln + i * 32);
                m = fmaxf(m, v[i]);
            }
#pragma unroll
            for (int off = 16; off > 0; off >>= 1)
                m = fmaxf(m, __shfl_xor_sync(0xffffffffu, m, off));
            float sm = 0.0f;
#pragma unroll
            for (int i = 0; i < 16; i++) sm += expf(v[i] - m);
#pragma unroll
            for (int off = 16; off > 0; off >>= 1)
                sm += __shfl_xor_sync(0xffffffffu, sm, off);
            float lsv = m + logf(sm);
#pragma unroll
            for (int i = 0; i < 16; i++) p[ln + i * 32] = v[i] - lsv;
        }
    }
}

// ---------------------------------------------------------------------------
extern "C" void kernel_launch(void* const* d_in, const int* in_sizes, int n_in,
                              void* d_out, int out_size)
{
    const float* xb = (const float*)d_in[0];
    const float* h0 = (const float*)d_in[1];
    const float* Wx = (const float*)d_in[2];
    const float* bx = (const float*)d_in[3];
    const float* Wh = (const float*)d_in[4];
    const float* bh = (const float*)d_in[5];
    const float* Wo = (const float*)d_in[6];
    const float* bo = (const float*)d_in[7];
    float* out = (float*)d_out;

    sgru_kernel<<<NBLK, NTHR>>>(xb, h0, Wx, bx, Wh, bh, Wo, bo, out);
}

// round 10
// speedup vs baseline: 1.5585x; 1.0116x over previous
#include <cuda_runtime.h>
#include <math.h>
#include <stdint.h>

#define B_   256
#define T_   256
#define INSZ 512
#define HD   1024
#define NBLK 128
#define NTHR 512

typedef unsigned long long u64;

// Ping-pong hidden state [2][B][4][HD] and inter-stack pred buffers [2][B][INSZ]
__device__ float g_h[2][B_ * 4 * HD];
__device__ float g_pred[2][B_ * INSZ];

// Grid barrier state (sense-reversing; self-resetting count)
__device__ unsigned g_count;
__device__ volatile unsigned g_sense;

__device__ __forceinline__ void grid_barrier(unsigned& ls)
{
    __syncthreads();
    if (threadIdx.x == 0) {
        unsigned s = ls ^ 1u;
        __threadfence();
        if (atomicAdd(&g_count, 1u) == NBLK - 1) {
            g_count = 0;
            __threadfence();
            g_sense = s;            // release
        } else {
            while (g_sense != s) { __nanosleep(32); }
        }
        __threadfence();            // acquire
        ls = s;
    }
    __syncthreads();
}

// ---- packed f32x2 helpers ----
__device__ __forceinline__ u64 pack2(float lo, float hi)
{ u64 r; asm("mov.b64 %0, {%1, %2};" : "=l"(r) : "f"(lo), "f"(hi)); return r; }
__device__ __forceinline__ void unpack2(u64 v, float& lo, float& hi)
{ asm("mov.b64 {%0, %1}, %2;" : "=f"(lo), "=f"(hi) : "l"(v)); }
__device__ __forceinline__ void ffma2(u64& d, u64 a, u64 b)
{ asm("fma.rn.f32x2 %0, %1, %2, %0;" : "+l"(d) : "l"(a), "l"(b)); }
__device__ __forceinline__ u64 addf2(u64 a, u64 b)
{ u64 r; asm("add.rn.f32x2 %0, %1, %2;" : "=l"(r) : "l"(a), "l"(b)); return r; }

// smem byte offsets
#define OFF_AS  0                     // float [64][68]
#define OFF_WS  17408                 // float [3][64][36]
#define OFF_RED 45056                 // u64 [3*128][33]
#define SMEMB   146432

// ---------------------------------------------------------------------------
// 3-gate GEMM accumulate: 32j x 64b tile, 512 threads, chunk K=64.
// k-loop of each chunk split across 4 thread-quarters (kh = quarter*16).
// Output microtile 4j x 4b on the 128 quarter-0 threads after reduction.
// ---------------------------------------------------------------------------
__device__ __forceinline__ void accum3(
    const float* __restrict__ A, int astride,
    const float* __restrict__ W, int K, int nk,
    u64 (&au)[2][4], u64 (&ar)[2][4], u64 (&an)[2][4],
    int tx, int ty, int kh, int tid,
    float (*As)[68], float (*Wu)[36], float (*Wr)[36], float (*Wn)[36])
{
    const int bb = ((tid) >> 4) & 63, kqa = tid & 15;          // A loader (i stride 512)
    const int jj = tid >> 4, kqw = tid & 15;                   // W loader (jj 0..31)
    float4 pa[2], pu, pr, pn;

#pragma unroll
    for (int i = 0; i < 2; i++) {
        int lin = tid + i * 512;
        pa[i] = __ldcg((const float4*)(A + (size_t)(lin >> 4) * astride + (lin & 15) * 4));
    }
    {
        size_t ro = (size_t)jj * K + kqw * 4;
        pu = *(const float4*)(W + ro);
        pr = *(const float4*)(W + (size_t)HD * K + ro);
        pn = *(const float4*)(W + (size_t)(2 * HD) * K + ro);
    }

    for (int k0 = 0; k0 < nk; k0 += 64) {
        __syncthreads();
#pragma unroll
        for (int i = 0; i < 2; i++) {
            int lin = tid + i * 512;
            int b2 = lin >> 4, kq = lin & 15;
            As[kq * 4 + 0][b2] = pa[i].x; As[kq * 4 + 1][b2] = pa[i].y;
            As[kq * 4 + 2][b2] = pa[i].z; As[kq * 4 + 3][b2] = pa[i].w;
        }
        Wu[kqw * 4 + 0][jj] = pu.x; Wu[kqw * 4 + 1][jj] = pu.y;
        Wu[kqw * 4 + 2][jj] = pu.z; Wu[kqw * 4 + 3][jj] = pu.w;
        Wr[kqw * 4 + 0][jj] = pr.x; Wr[kqw * 4 + 1][jj] = pr.y;
        Wr[kqw * 4 + 2][jj] = pr.z; Wr[kqw * 4 + 3][jj] = pr.w;
        Wn[kqw * 4 + 0][jj] = pn.x; Wn[kqw * 4 + 1][jj] = pn.y;
        Wn[kqw * 4 + 2][jj] = pn.z; Wn[kqw * 4 + 3][jj] = pn.w;
        __syncthreads();
        int kn = k0 + 64;
        if (kn < nk) {
#pragma unroll
            for (int i = 0; i < 2; i++) {
                int lin = tid + i * 512;
                pa[i] = __ldcg((const float4*)(A + (size_t)(lin >> 4) * astride + (kn + (lin & 15) * 4)));
            }
            size_t ro = (size_t)jj * K + (kn + kqw * 4);
            pu = *(const float4*)(W + ro);
            pr = *(const float4*)(W + (size_t)HD * K + ro);
            pn = *(const float4*)(W + (size_t)(2 * HD) * K + ro);
        }
#pragma unroll
        for (int kk = 0; kk < 16; kk++) {
            int ka = kh + kk;
            float4 a4 = *(const float4*)&As[ka][ty * 4];
            u64 Ab[4];
            Ab[0] = pack2(a4.x, a4.x); Ab[1] = pack2(a4.y, a4.y);
            Ab[2] = pack2(a4.z, a4.z); Ab[3] = pack2(a4.w, a4.w);
            ulonglong2 wu = *(const ulonglong2*)&Wu[ka][tx * 4];
            ulonglong2 wr = *(const ulonglong2*)&Wr[ka][tx * 4];
            ulonglong2 wn = *(const ulonglong2*)&Wn[ka][tx * 4];
#pragma unroll
            for (int i = 0; i < 4; i++) {
                ffma2(au[0][i], Ab[i], wu.x); ffma2(au[1][i], Ab[i], wu.y);
                ffma2(ar[0][i], Ab[i], wr.x); ffma2(ar[1][i], Ab[i], wr.y);
                ffma2(an[0][i], Ab[i], wn.x); ffma2(an[1][i], Ab[i], wn.y);
            }
        }
    }
    (void)bb; (void)kqa;
}

// Pred accumulate: 16o x 64b tile, 512 threads, chunk K=64, k-split quarters.
__device__ __forceinline__ void accum1(
    const float* __restrict__ A, int astride,
    const float* __restrict__ W, int wstride, int nk,
    u64 (&acc)[2][2],            // [o][bpair]
    int tx, int ty, int kh, int tid,
    float (*As)[68], float (*Ws)[36])
{
    const int jj = tid >> 4, kqw = tid & 15;   // only tid<256 loads W (jj 0..15)
    float4 pa[2], pw;

#pragma unroll
    for (int i = 0; i < 2; i++) {
        int lin = tid + i * 512;
        pa[i] = __ldcg((const float4*)(A + (size_t)(lin >> 4) * astride + (lin & 15) * 4));
    }
    if (tid < 256)
        pw = *(const float4*)(W + (size_t)jj * wstride + kqw * 4);

    for (int k0 = 0; k0 < nk; k0 += 64) {
        __syncthreads();
#pragma unroll
        for (int i = 0; i < 2; i++) {
            int lin = tid + i * 512;
            int b2 = lin >> 4, kq = lin & 15;
            As[kq * 4 + 0][b2] = pa[i].x; As[kq * 4 + 1][b2] = pa[i].y;
            As[kq * 4 + 2][b2] = pa[i].z; As[kq * 4 + 3][b2] = pa[i].w;
        }
        if (tid < 256) {
            Ws[kqw * 4 + 0][jj] = pw.x; Ws[kqw * 4 + 1][jj] = pw.y;
            Ws[kqw * 4 + 2][jj] = pw.z; Ws[kqw * 4 + 3][jj] = pw.w;
        }
        __syncthreads();
        int kn = k0 + 64;
        if (kn < nk) {
#pragma unroll
            for (int i = 0; i < 2; i++) {
                int lin = tid + i * 512;
                pa[i] = __ldcg((const float4*)(A + (size_t)(lin >> 4) * astride + (kn + (lin & 15) * 4)));
            }
            if (tid < 256)
                pw = *(const float4*)(W + (size_t)jj * wstride + (kn + kqw * 4));
        }
#pragma unroll
        for (int kk = 0; kk < 16; kk++) {
            int ka = kh + kk;
            ulonglong2 a2 = *(const ulonglong2*)&As[ka][ty * 4];   // (b0,b1),(b2,b3)
            float2 wf = *(const float2*)&Ws[ka][tx * 2];
            u64 W0 = pack2(wf.x, wf.x);
            u64 W1 = pack2(wf.y, wf.y);
            ffma2(acc[0][0], W0, a2.x); ffma2(acc[0][1], W0, a2.y);
            ffma2(acc[1][0], W1, a2.x); ffma2(acc[1][1], W1, a2.y);
        }
    }
}

// ---------------------------------------------------------------------------
// One persistent kernel. grid = 128 blocks, 512 threads (4 warps/SMSP).
// ---------------------------------------------------------------------------
__global__ void __launch_bounds__(NTHR) sgru_kernel(
    const float* __restrict__ xb, const float* __restrict__ h0,
    const float* __restrict__ Wx, const float* __restrict__ bx,
    const float* __restrict__ Wh, const float* __restrict__ bh,
    const float* __restrict__ Wo, const float* __restrict__ bo,
    float* __restrict__ out)
{
    extern __shared__ __align__(16) char smx[];
    float (*As)[68] = (float (*)[68])(smx + OFF_AS);
    float (*Wu)[36] = (float (*)[36])(smx + OFF_WS);
    float (*Wr)[36] = (float (*)[36])(smx + OFF_WS + 9216);
    float (*Wn)[36] = (float (*)[36])(smx + OFF_WS + 18432);
    u64* red = (u64*)(smx + OFF_RED);

    int tid = threadIdx.x;
    int bid = blockIdx.x;
    int tid2 = tid & 127, quarter = tid >> 7, kh = quarter * 16;
    unsigned ls = g_sense;   // read before any block can flip it

    // ---- init: h0 -> g_h[0] ----
    {
        int g = bid * NTHR + tid;
        const float4* s4 = (const float4*)h0;
        float4* d4 = (float4*)g_h[0];
#pragma unroll 1
        for (int i = g; i < B_ * 4 * HD / 4; i += NBLK * NTHR) d4[i] = s4[i];
    }
    grid_barrier(ls);

#pragma unroll 1
    for (int t = 0; t < T_; t++) {
        int rd = t & 1, wr = rd ^ 1;
#pragma unroll 1
        for (int s = 0; s < 4; s++) {
            int wi = (s == 3) ? 2 : s;   // faithful to the source bug

            const float* x;
            int xstride;
            if (s == 0) { x = xb + (size_t)t * INSZ; xstride = T_ * INSZ; }
            else        { x = g_pred[(s - 1) & 1];   xstride = INSZ; }

            // ===== gate phase: 32 j-tiles (32) x 4 b-tiles (64) =====
            {
                int tx = tid2 & 7, ty = tid2 >> 3;   // 8 x 4j = 32j, 16 x 4b = 64b
                int j0 = (bid & 31) * 32;
                int b0 = (bid >> 5) * 64;
                const float* Wxp = Wx + (size_t)wi * 3 * HD * INSZ + (size_t)j0 * INSZ;
                const float* Whp = Wh + (size_t)wi * 3 * HD * HD + (size_t)j0 * HD;
                const float* bx3 = bx + wi * 3 * HD;
                const float* bh3 = bh + wi * 3 * HD;
                const float* hrd = g_h[rd] + s * HD;
                float* hwr = g_h[wr] + s * HD;

                u64 au[2][4], ar[2][4], axn[2][4], ahn[2][4];
                if (quarter == 0) {
#pragma unroll
                    for (int p = 0; p < 2; p++) {
                        int jg = j0 + tx * 4 + p * 2;
                        u64 bu = pack2(bx3[jg] + bh3[jg], bx3[jg + 1] + bh3[jg + 1]);
                        u64 br = pack2(bx3[HD + jg] + bh3[HD + jg],
                                       bx3[HD + jg + 1] + bh3[HD + jg + 1]);
                        u64 bxn = pack2(bx3[2 * HD + jg], bx3[2 * HD + jg + 1]);
                        u64 bhn = pack2(bh3[2 * HD + jg], bh3[2 * HD + jg + 1]);
#pragma unroll
                        for (int i = 0; i < 4; i++) {
                            au[p][i] = bu; ar[p][i] = br;
                            axn[p][i] = bxn; ahn[p][i] = bhn;
                        }
                    }
                } else {
#pragma unroll
                    for (int p = 0; p < 2; p++)
#pragma unroll
                        for (int i = 0; i < 4; i++) {
                            au[p][i] = 0; ar[p][i] = 0;
                            axn[p][i] = 0; ahn[p][i] = 0;
                        }
                }
                accum3(x + (size_t)b0 * xstride, xstride, Wxp, INSZ, INSZ,
                       au, ar, axn, tx, ty, kh, tid, As, Wu, Wr, Wn);
                accum3(hrd + (size_t)b0 * (4 * HD), 4 * HD, Whp, HD, HD,
                       au, ar, ahn, tx, ty, kh, tid, As, Wu, Wr, Wn);

                // single-round cross-quarter reduction (32 u64 per thread)
                __syncthreads();
                if (quarter) {
                    u64* rp = red + ((size_t)(quarter - 1) * 128 + tid2) * 33;
#pragma unroll
                    for (int p = 0; p < 2; p++)
#pragma unroll
                        for (int i = 0; i < 4; i++) {
                            rp[p * 4 + i] = au[p][i];
                            rp[8 + p * 4 + i] = ar[p][i];
                            rp[16 + p * 4 + i] = axn[p][i];
                            rp[24 + p * 4 + i] = ahn[p][i];
                        }
                }
                __syncthreads();
                if (!quarter) {
#pragma unroll
                    for (int qq = 0; qq < 3; qq++) {
                        u64* rp = red + ((size_t)qq * 128 + tid2) * 33;
#pragma unroll
                        for (int p = 0; p < 2; p++)
#pragma unroll
                            for (int i = 0; i < 4; i++) {
                                au[p][i] = addf2(au[p][i], rp[p * 4 + i]);
                                ar[p][i] = addf2(ar[p][i], rp[8 + p * 4 + i]);
                                axn[p][i] = addf2(axn[p][i], rp[16 + p * 4 + i]);
                                ahn[p][i] = addf2(ahn[p][i], rp[24 + p * 4 + i]);
                            }
                    }
#pragma unroll
                    for (int i = 0; i < 4; i++) {
                        int b = b0 + ty * 4 + i;
                        int jg = j0 + tx * 4;
                        float4 hold = __ldcg((const float4*)(hrd + (size_t)b * (4 * HD) + jg));
                        float ho[4] = {hold.x, hold.y, hold.z, hold.w};
                        float uv[4], rv[4], xnv[4], hnv[4];
#pragma unroll
                        for (int p = 0; p < 2; p++) {
                            unpack2(au[p][i], uv[p * 2], uv[p * 2 + 1]);
                            unpack2(ar[p][i], rv[p * 2], rv[p * 2 + 1]);
                            unpack2(axn[p][i], xnv[p * 2], xnv[p * 2 + 1]);
                            unpack2(ahn[p][i], hnv[p * 2], hnv[p * 2 + 1]);
                        }
                        float4 hv;
                        float* hvp = &hv.x;
#pragma unroll
                        for (int jj = 0; jj < 4; jj++) {
                            float u = 1.0f / (1.0f + expf(-uv[jj]));
                            float r = 1.0f / (1.0f + expf(-rv[jj]));
                            float n = tanhf(xnv[jj] + r * hnv[jj]);
                            hvp[jj] = u * ho[jj] + (1.0f - u) * n;
                        }
                        *(float4*)(hwr + (size_t)b * (4 * HD) + jg) = hv;
                    }
                }
            }
            grid_barrier(ls);

            // ===== pred phase: 32 o-tiles (16) x 4 b-tiles (64) =====
            {
                int tx = tid2 & 7, ty = tid2 >> 3;   // 8 x 2o = 16o, 16 x 4b = 64b
                int o0 = (bid & 31) * 16;
                int b0 = (bid >> 5) * 64;
                const float* Wop = Wo + (size_t)wi * INSZ * (HD + INSZ) + (size_t)o0 * (HD + INSZ);
                const float* bop = bo + wi * INSZ;
                const float* hn = g_h[wr] + s * HD;

                u64 acc[2][2];   // [o][bpair]
                if (quarter == 0) {
                    acc[0][0] = acc[0][1] = pack2(bop[o0 + tx * 2], bop[o0 + tx * 2]);
                    acc[1][0] = acc[1][1] = pack2(bop[o0 + tx * 2 + 1], bop[o0 + tx * 2 + 1]);
                } else {
                    acc[0][0] = acc[0][1] = 0;
                    acc[1][0] = acc[1][1] = 0;
                }

                accum1(x + (size_t)b0 * xstride, xstride,
                       Wop, HD + INSZ, INSZ, acc, tx, ty, kh, tid, As, Wu);
                accum1(hn + (size_t)b0 * (4 * HD), 4 * HD,
                       Wop + INSZ, HD + INSZ, HD, acc, tx, ty, kh, tid, As, Wu);

                __syncthreads();
                if (quarter) {
                    u64* rp = red + ((size_t)(quarter - 1) * 128 + tid2) * 33;
                    rp[0] = acc[0][0]; rp[1] = acc[0][1];
                    rp[2] = acc[1][0]; rp[3] = acc[1][1];
                }
                __syncthreads();
                if (!quarter) {
#pragma unroll
                    for (int qq = 0; qq < 3; qq++) {
                        u64* rp = red + ((size_t)qq * 128 + tid2) * 33;
                        acc[0][0] = addf2(acc[0][0], rp[0]);
                        acc[0][1] = addf2(acc[0][1], rp[1]);
                        acc[1][0] = addf2(acc[1][0], rp[2]);
                        acc[1][1] = addf2(acc[1][1], rp[3]);
                    }

                    float* outp; int ostr;
                    if (s == 3) { outp = out + (size_t)t * INSZ; ostr = T_ * INSZ; }
                    else        { outp = g_pred[s & 1];          ostr = INSZ; }

                    float o0b[4], o1b[4];
                    unpack2(acc[0][0], o0b[0], o0b[1]); unpack2(acc[0][1], o0b[2], o0b[3]);
                    unpack2(acc[1][0], o1b[0], o1b[1]); unpack2(acc[1][1], o1b[2], o1b[3]);
#pragma unroll
                    for (int i = 0; i < 4; i++) {
                        int b = b0 + ty * 4 + i;
                        float2 v = make_float2(o0b[i], o1b[i]);
                        *(float2*)(outp + (size_t)b * ostr + (o0 + tx * 2)) = v;
                    }
                }
            }
            grid_barrier(ls);
        }
    }

    // ---- copy final h (in g_h[0]) to out tail ----
    {
        int g = bid * NTHR + tid;
        const float4* s4 = (const float4*)g_h[0];
        float4* d4 = (float4*)(out + (size_t)B_ * T_ * INSZ);
#pragma unroll 1
        for (int i = g; i < B_ * 4 * HD / 4; i += NBLK * NTHR) d4[i] = __ldcg(s4 + i);
    }

    // ---- log_softmax over each 512-wide pred row ----
    {
        int w = tid >> 5, ln = tid & 31;      // 16 warps per block
        int gw = bid * 16 + w;
#pragma unroll 1
        for (int r = gw; r < B_ * T_; r += NBLK * 16) {
            float* p = out + (size_t)r * INSZ;
            float v[16];
            float m = -1e30f;
#pragma unroll
            for (int i = 0; i < 16; i++) {
                v[i] = __ldcg(p + ln + i * 32);
                m = fmaxf(m, v[i]);
            }
#pragma unroll
            for (int off = 16; off > 0; off >>= 1)
                m = fmaxf(m, __shfl_xor_sync(0xffffffffu, m, off));
            float sm = 0.0f;
#pragma unroll
            for (int i = 0; i < 16; i++) sm += expf(v[i] - m);
#pragma unroll
            for (int off = 16; off > 0; off >>= 1)
                sm += __shfl_xor_sync(0xffffffffu, sm, off);
            float lsv = m + logf(sm);
#pragma unroll
            for (int i = 0; i < 16; i++) p[ln + i * 32] = v[i] - lsv;
        }
    }
}

// ---------------------------------------------------------------------------
extern "C" void kernel_launch(void* const* d_in, const int* in_sizes, int n_in,
                              void* d_out, int out_size)
{
    const float* xb = (const float*)d_in[0];
    const float* h0 = (const float*)d_in[1];
    const float* Wx = (const float*)d_in[2];
    const float* bx = (const float*)d_in[3];
    const float* Wh = (const float*)d_in[4];
    const float* bh = (const float*)d_in[5];
    const float* Wo = (const float*)d_in[6];
    const float* bo = (const float*)d_in[7];
    float* out = (float*)d_out;

    cudaFuncSetAttribute(sgru_kernel, cudaFuncAttributeMaxDynamicSharedMemorySize, SMEMB);
    sgru_kernel<<<NBLK, NTHR, SMEMB>>>(xb, h0, Wx, bx, Wh, bh, Wo, bo, out);
}